// round 1
// baseline (speedup 1.0000x reference)
#include <cuda_runtime.h>
#include <math.h>

#define BATCH 2
#define SEQ   4096
#define EMB   512
#define NH    8
#define HD    64
#define BHTOT (BATCH*NH)
#define NROWS (BATCH*SEQ)

// ---------------- scratch (static device globals; no allocation) ----------------
__device__ float g_Q[BHTOT*SEQ*HD];      // [B,H,S,HD]
__device__ float g_K[BHTOT*SEQ*HD];
__device__ float g_V[BHTOT*SEQ*HD];
__device__ float g_ctx[NROWS*EMB];       // [B*S, E]
__device__ float g_maskbias[NROWS];      // 0 or -1e30 per (b, key)

// ---------------- mask: detect dtype (bool/int8 vs int32/float32) and expand ----
__global__ void mask_kernel(const unsigned char* __restrict__ mraw)
{
    __shared__ int flag;
    if (threadIdx.x == 0) flag = 0;
    __syncthreads();
    // If the mask is serialized 1 byte/elem, nonzero bytes appear inside the
    // first NROWS bytes. If 4 bytes/elem (int32/float32), the first NROWS bytes
    // cover only the first NROWS/4 entries, which are all zero for this mask.
    int any = 0;
    for (int i = threadIdx.x; i < NROWS; i += blockDim.x)
        any |= (mraw[i] != 0);
    if (any) atomicOr(&flag, 1);
    __syncthreads();
    const int bytemode = flag;
    const int* mi = (const int*)mraw;
    for (int i = threadIdx.x; i < NROWS; i += blockDim.x) {
        bool masked = bytemode ? (mraw[i] != 0) : (mi[i] != 0);
        g_maskbias[i] = masked ? -1e30f : 0.0f;
    }
}

// ---------------- GEMM: C[n,e] = sum_k X[n,k]*W[e,k] + bias[e] ----------------
// mode 0: write to [B,H,S,HD] layout (QKV projection)
// mode 1: write row-major [N,E] (output projection)
#define GBM 128
#define GBN 128
#define GBK 16
#define GPAD 132

__global__ __launch_bounds__(256)
void gemm_kernel(const float* __restrict__ X, const float* __restrict__ W,
                 const float* __restrict__ bias, float* __restrict__ out, int mode)
{
    __shared__ __align__(16) float Xs[GBK][GPAD];
    __shared__ __align__(16) float Ws[GBK][GPAD];
    const int tid = threadIdx.x;
    const int tx = tid & 15;
    const int ty = tid >> 4;
    const int rowbase = blockIdx.y * GBM;
    const int colbase = blockIdx.x * GBN;

    float acc[8][8];
#pragma unroll
    for (int i = 0; i < 8; i++)
#pragma unroll
        for (int j = 0; j < 8; j++) acc[i][j] = 0.0f;

    for (int kt = 0; kt < EMB; kt += GBK) {
#pragma unroll
        for (int p = 0; p < 2; p++) {
            int idx = tid + p * 256;      // 0..511
            int r   = idx >> 2;           // 0..127
            int kq  = (idx & 3) << 2;     // 0,4,8,12
            float4 xv = *(const float4*)(X + (size_t)(rowbase + r) * EMB + kt + kq);
            Xs[kq + 0][r] = xv.x; Xs[kq + 1][r] = xv.y;
            Xs[kq + 2][r] = xv.z; Xs[kq + 3][r] = xv.w;
            float4 wv = *(const float4*)(W + (size_t)(colbase + r) * EMB + kt + kq);
            Ws[kq + 0][r] = wv.x; Ws[kq + 1][r] = wv.y;
            Ws[kq + 2][r] = wv.z; Ws[kq + 3][r] = wv.w;
        }
        __syncthreads();
#pragma unroll
        for (int k = 0; k < GBK; k++) {
            float a[8], bb[8];
            *(float4*)&a[0]  = *(const float4*)&Xs[k][ty * 8];
            *(float4*)&a[4]  = *(const float4*)&Xs[k][ty * 8 + 4];
            *(float4*)&bb[0] = *(const float4*)&Ws[k][tx * 8];
            *(float4*)&bb[4] = *(const float4*)&Ws[k][tx * 8 + 4];
#pragma unroll
            for (int i = 0; i < 8; i++)
#pragma unroll
                for (int j = 0; j < 8; j++)
                    acc[i][j] = fmaf(a[i], bb[j], acc[i][j]);
        }
        __syncthreads();
    }

#pragma unroll
    for (int i = 0; i < 8; i++) {
        const int r = rowbase + ty * 8 + i;
#pragma unroll
        for (int j = 0; j < 8; j++) {
            const int e = colbase + tx * 8 + j;
            float v = acc[i][j] + bias[e];
            if (mode == 0) {
                int bb_ = r >> 12;            // / SEQ
                int s   = r & (SEQ - 1);
                int hh  = e >> 6;             // / HD
                int d   = e & (HD - 1);
                out[(((size_t)(bb_ * NH + hh)) * SEQ + s) * HD + d] = v;
            } else {
                out[(size_t)r * EMB + e] = v;
            }
        }
    }
}

// ---------------- RoPE on Q and K (layout [B*H, S, HD]) ----------------
__global__ void rope_kernel()
{
    const int total = BHTOT * SEQ * (HD / 2);
    int gid = blockIdx.x * blockDim.x + threadIdx.x;
    if (gid >= total) return;
    int i   = gid & 31;          // 0..31 (half-dim index)
    int row = gid >> 5;          // 0..BHTOT*SEQ-1
    int s   = row & (SEQ - 1);
    float inv = powf(10000.0f, -(float)i / 32.0f);   // base^(-2i/HD)
    float ang = (float)s * inv;
    float sn, cs;
    sincosf(ang, &sn, &cs);
    size_t base = (size_t)row * HD;
    float q0 = g_Q[base + i], q1 = g_Q[base + i + 32];
    g_Q[base + i]      = q0 * cs - q1 * sn;
    g_Q[base + i + 32] = q1 * cs + q0 * sn;
    float k0 = g_K[base + i], k1 = g_K[base + i + 32];
    g_K[base + i]      = k0 * cs - k1 * sn;
    g_K[base + i + 32] = k1 * cs + k0 * sn;
}

// ---------------- Flash attention: 1 q-row per thread ----------------
#define FBM 128   // q rows per block (= threads per block)
#define FBN 64    // keys per tile

__global__ __launch_bounds__(FBM)
void flash_kernel()
{
    __shared__ __align__(16) float Ks[FBN * HD];
    __shared__ __align__(16) float Vs[FBN * HD];
    __shared__ float mb[FBN];

    const int tid = threadIdx.x;
    const int bh  = blockIdx.y;
    const int b   = bh >> 3;
    const int h   = bh & 7;
    const int row = blockIdx.x * FBM + tid;

    // load q row into registers
    const float* Qg = g_Q + ((size_t)bh * SEQ + row) * HD;
    float q[HD];
#pragma unroll
    for (int d = 0; d < HD; d += 4) {
        float4 v = *(const float4*)(Qg + d);
        q[d] = v.x; q[d + 1] = v.y; q[d + 2] = v.z; q[d + 3] = v.w;
    }
    float o[HD];
#pragma unroll
    for (int d = 0; d < HD; d++) o[d] = 0.0f;
    float m = -INFINITY, l = 0.0f;
    const float scale = 0.125f;   // 1/sqrt(64)

    for (int kt = 0; kt < SEQ / FBN; ++kt) {
        __syncthreads();
        const float4* Kg = (const float4*)(g_K + ((size_t)bh * SEQ + kt * FBN) * HD);
        const float4* Vg = (const float4*)(g_V + ((size_t)bh * SEQ + kt * FBN) * HD);
        float4* Ks4 = (float4*)Ks;
        float4* Vs4 = (float4*)Vs;
#pragma unroll
        for (int p = 0; p < (FBN * HD / 4) / FBM; p++) {  // 8 iters
            int idx = tid + p * FBM;
            Ks4[idx] = Kg[idx];
            Vs4[idx] = Vg[idx];
        }
        if (tid < FBN) mb[tid] = g_maskbias[b * SEQ + kt * FBN + tid];
        __syncthreads();

        // scores for this tile
        float sj[FBN];
        float smax = -INFINITY;
#pragma unroll
        for (int j = 0; j < FBN; j++) {
            const float4* kr = (const float4*)(Ks + j * HD);
            float a0 = 0.f, a1 = 0.f, a2 = 0.f, a3 = 0.f;
#pragma unroll
            for (int t = 0; t < 16; t++) {
                float4 kv = kr[t];
                a0 = fmaf(q[4 * t + 0], kv.x, a0);
                a1 = fmaf(q[4 * t + 1], kv.y, a1);
                a2 = fmaf(q[4 * t + 2], kv.z, a2);
                a3 = fmaf(q[4 * t + 3], kv.w, a3);
            }
            float sv = (a0 + a1) + (a2 + a3);
            sv = fmaf(sv, scale, mb[j]);
            sj[j] = sv;
            smax = fmaxf(smax, sv);
        }

        // online softmax update
        float mnew = fmaxf(m, smax);
        float corr = __expf(m - mnew);
        l *= corr;
#pragma unroll
        for (int d = 0; d < HD; d++) o[d] *= corr;

        float lsum = 0.0f;
#pragma unroll
        for (int j = 0; j < FBN; j++) {
            float p = __expf(sj[j] - mnew);
            lsum += p;
            const float4* vr = (const float4*)(Vs + j * HD);
#pragma unroll
            for (int t = 0; t < 16; t++) {
                float4 v = vr[t];
                o[4 * t + 0] = fmaf(p, v.x, o[4 * t + 0]);
                o[4 * t + 1] = fmaf(p, v.y, o[4 * t + 1]);
                o[4 * t + 2] = fmaf(p, v.z, o[4 * t + 2]);
                o[4 * t + 3] = fmaf(p, v.w, o[4 * t + 3]);
            }
        }
        l += lsum;
        m = mnew;
    }

    const float invl = 1.0f / l;
    float* outp = g_ctx + ((size_t)b * SEQ + row) * EMB + h * HD;
#pragma unroll
    for (int d = 0; d < HD; d += 4) {
        float4 v;
        v.x = o[d] * invl; v.y = o[d + 1] * invl;
        v.z = o[d + 2] * invl; v.w = o[d + 3] * invl;
        *(float4*)(outp + d) = v;
    }
}

// ---------------- launch ----------------
extern "C" void kernel_launch(void* const* d_in, const int* in_sizes, int n_in,
                              void* d_out, int out_size)
{
    const float* query = (const float*)d_in[0];
    const float* key_  = (const float*)d_in[1];
    const float* value = (const float*)d_in[2];
    const float* Wq = (const float*)d_in[3];
    const float* bq = (const float*)d_in[4];
    const float* Wk = (const float*)d_in[5];
    const float* bk = (const float*)d_in[6];
    const float* Wv = (const float*)d_in[7];
    const float* bv = (const float*)d_in[8];
    const float* Wo = (const float*)d_in[9];
    const float* bo = (const float*)d_in[10];
    const unsigned char* mask = (const unsigned char*)d_in[11];

    float *Qd, *Kd, *Vd, *Cd;
    cudaGetSymbolAddress((void**)&Qd, g_Q);
    cudaGetSymbolAddress((void**)&Kd, g_K);
    cudaGetSymbolAddress((void**)&Vd, g_V);
    cudaGetSymbolAddress((void**)&Cd, g_ctx);

    mask_kernel<<<1, 256>>>(mask);

    dim3 ggrid(EMB / GBN, NROWS / GBM);   // (4, 64)
    gemm_kernel<<<ggrid, 256>>>(query, Wq, bq, Qd, 0);
    gemm_kernel<<<ggrid, 256>>>(key_,  Wk, bk, Kd, 0);
    gemm_kernel<<<ggrid, 256>>>(value, Wv, bv, Vd, 0);

    const int rope_total = BHTOT * SEQ * (HD / 2);
    rope_kernel<<<(rope_total + 255) / 256, 256>>>();

    flash_kernel<<<dim3(SEQ / FBM, BHTOT), FBM>>>();

    gemm_kernel<<<ggrid, 256>>>(Cd, Wo, bo, (float*)d_out, 1);
}